// round 13
// baseline (speedup 1.0000x reference)
#include <cuda_runtime.h>
#include <cuda_bf16.h>
#include <cstdint>

// ---------------- problem dims (fixed by dataset) ----------------
#define T_STEPS 512
#define BATCH   128
#define SDIM    1024
#define ODIM    256
#define JDIM    (SDIM + ODIM)   // 1280

// ---------------- tiling (R4 topology, fp8 operands) ----------------
#define NB 4                 // batch tiles (independent recurrence groups)
#define NJ 32                // j tiles
#define BT 32                // batch rows per CTA
#define JT 40                // j cols per CTA
#define NCTAS (NB * NJ)      // 128 CTAs, one per SM
#define NTHREADS 256
#define NWARPS 8
#define KSLICE 128           // K bytes (fp8 elems) per warp slice
#define CLUSTER 4
#define ROWS_PER_CTA (BT / CLUSTER)   // 8 rows loaded+multicast per CTA
#define NPROD 26             // jtiles 0..25 produce h columns
#define ROW_BYTES 1024       // fp8 G row in gmem
#define GSTRIDE_B 1040       // smem row stride bytes (1024 + 16 pad)
#define EPT 5

// scaling: W stored x64, G stored x16 -> y_true = mma / 1024
#define Y_INV (1.0f / 1024.0f)

// smem layout (bytes)
#define SG_BYTES (BT * GSTRIDE_B)              // 33280
#define SP_BYTES (NWARPS * BT * JT * 4)        // 40960
#define SMEM_TOTAL (SG_BYTES + SP_BYTES + 16)  // + two mbarriers

// ---------------- device globals ----------------
__device__ __align__(16) uint8_t g_W[(size_t)JDIM * SDIM];      // e4m3, x64
__device__ __align__(16) uint8_t g_G[2][(size_t)BATCH * SDIM];  // e4m3, tanh(h) x16
__device__ unsigned g_slots0[NB * 32];
__device__ unsigned g_slots1[NB * 32];

// ---------------- helpers ----------------
__device__ __forceinline__ unsigned ld_acq(const unsigned* p) {
    unsigned v;
    asm volatile("ld.acquire.gpu.global.u32 %0, [%1];" : "=r"(v) : "l"(p));
    return v;
}
__device__ __forceinline__ void st_rel(unsigned* p, unsigned v) {
    asm volatile("st.release.gpu.global.u32 [%0], %1;" :: "l"(p), "r"(v) : "memory");
}
__device__ __forceinline__ float tanh_fast(float v) {
    float r;
    asm("tanh.approx.f32 %0, %1;" : "=f"(r) : "f"(v));
    return r;
}
// single-instruction f32 -> e4m3 (saturating); low byte of the x2 result
__device__ __forceinline__ uint8_t f32_to_e4m3(float v) {
    unsigned short s;
    asm("cvt.rn.satfinite.e4m3x2.f32 %0, %1, %1;" : "=h"(s) : "f"(v));
    return (uint8_t)s;
}
__device__ __forceinline__ void mma_fp8(float c[4], const unsigned a[4],
                                        unsigned b0, unsigned b1) {
    asm volatile(
        "mma.sync.aligned.m16n8k32.row.col.f32.e4m3.e4m3.f32 "
        "{%0,%1,%2,%3}, {%4,%5,%6,%7}, {%8,%9}, {%0,%1,%2,%3};\n"
        : "+f"(c[0]), "+f"(c[1]), "+f"(c[2]), "+f"(c[3])
        : "r"(a[0]), "r"(a[1]), "r"(a[2]), "r"(a[3]), "r"(b0), "r"(b1));
}
__device__ __forceinline__ void ldsm_x4(unsigned a[4], uint32_t addr) {
    asm volatile("ldmatrix.sync.aligned.m8n8.x4.shared.b16 {%0,%1,%2,%3}, [%4];"
                 : "=r"(a[0]), "=r"(a[1]), "=r"(a[2]), "=r"(a[3]) : "r"(addr));
}
__device__ __forceinline__ void mbar_wait(uint32_t mbar, unsigned parity) {
    asm volatile(
        "{\n\t"
        ".reg .pred P;\n\t"
        "WL_%=:\n\t"
        "mbarrier.try_wait.parity.acquire.cta.shared::cta.b64 P, [%0], %1, 0x989680;\n\t"
        "@P bra.uni WD_%=;\n\t"
        "bra.uni WL_%=;\n\t"
        "WD_%=:\n\t"
        "}" :: "r"(mbar), "r"(parity) : "memory");
}

// ---------------- init: fp8 weights (x64) + G0 = tanh(h_init) x16 ----------------
__global__ void trnn_init(const float* __restrict__ w_r, const float* __restrict__ w_o,
                          const float* __restrict__ h_init) {
    size_t stride = (size_t)gridDim.x * blockDim.x;
    size_t i0 = (size_t)blockIdx.x * blockDim.x + threadIdx.x;
    const size_t WR_N = (size_t)SDIM * SDIM;
    const size_t W_N  = (size_t)JDIM * SDIM;
    for (size_t i = i0; i < W_N; i += stride) {
        float v = (i < WR_N) ? w_r[i] : w_o[i - WR_N];
        g_W[i] = f32_to_e4m3(v * 64.0f);
    }
    for (size_t i = i0; i < (size_t)BATCH * SDIM; i += stride) {
        g_G[0][i] = f32_to_e4m3(tanhf(h_init[i]) * 16.0f);
    }
    if (i0 < NB * 32) { g_slots0[i0] = 0u; g_slots1[i0] = 0u; }
}

// ---------------- persistent kernel: R4 schedule verbatim, fp8 operands ----------------
__global__ void __launch_bounds__(NTHREADS, 1) __cluster_dims__(CLUSTER, 1, 1)
trnn_persistent(const float* __restrict__ x, const float* __restrict__ h_init,
                const float* __restrict__ b_r, const float* __restrict__ b_o,
                float* __restrict__ out) {
    extern __shared__ char smem[];
    uint8_t* sG = (uint8_t*)smem;
    float* sP = (float*)(smem + SG_BYTES);
    uint32_t mbar0 = (uint32_t)__cvta_generic_to_shared(smem + SG_BYTES + SP_BYTES);
    uint32_t mbar1 = mbar0 + 8;

    const int tid  = threadIdx.x;
    const int warp = tid >> 5;
    const int lane = tid & 31;
    const int grp  = lane >> 2;
    const int tig  = lane & 3;
    const int btile = blockIdx.x >> 5;
    const int jtile = blockIdx.x & 31;
    const int rank  = blockIdx.x & (CLUSTER - 1);
    const int b0 = btile * BT;
    const int j0 = jtile * JT;
    const int kw = warp * KSLICE;
    const bool producer = (jtile < NPROD);

    unsigned* my_slots = (rank < 2) ? &g_slots0[btile * 32] : &g_slots1[btile * 32];
    unsigned* rel0 = &g_slots0[btile * 32 + jtile];
    unsigned* rel1 = &g_slots1[btile * 32 + jtile];
    const uint32_t my_mbar = (rank < 2) ? mbar0 : mbar1;

    if (tid == 0) {
        asm volatile("mbarrier.init.shared.b64 [%0], 1;" :: "r"(mbar0) : "memory");
        asm volatile("mbarrier.init.shared.b64 [%0], 1;" :: "r"(mbar1) : "memory");
    }
    __syncthreads();
    asm volatile("barrier.cluster.arrive.aligned;" ::: "memory");
    asm volatile("barrier.cluster.wait.aligned;"   ::: "memory");

    // --- per-thread persistent epilogue state (e = d*256 + tid over 1280) ---
    int ej[EPT]; int ebl[EPT]; float hr[EPT]; float bv[EPT];
    #pragma unroll
    for (int d = 0; d < EPT; ++d) {
        int e = d * NTHREADS + tid;
        int bl = e / JT, jl = e - bl * JT;
        int j = j0 + jl;
        ej[d] = j; ebl[d] = bl;
        if (j < SDIM) {
            hr[d] = h_init[(size_t)(b0 + bl) * SDIM + j];
            bv[d] = b_r[j];
        } else {
            hr[d] = 0.f;
            bv[d] = b_o[j - SDIM];
        }
    }

    // --- W fragments (fp8, x64) persistent in registers: 4 k32-steps x 5 n x 2 = 40 regs ---
    unsigned Breg[4][5][2];
    #pragma unroll
    for (int ks = 0; ks < 4; ++ks) {
        #pragma unroll
        for (int ni = 0; ni < 5; ++ni) {
            int jr = j0 + ni * 8 + grp;
            const unsigned* wp = (const unsigned*)(g_W + (size_t)jr * SDIM + kw + ks * 32);
            Breg[ks][ni][0] = wp[tig];
            Breg[ks][ni][1] = wp[4 + tig];
        }
    }
    __syncthreads();

    // --- ldmatrix bases (rows 0-15 / 16-31; fp8 k32 frag == bf16 k16 byte layout) ---
    const uint32_t sGb = (uint32_t)__cvta_generic_to_shared(sG);
    const int rl = lane & 15;
    const uint32_t aBase0 = sGb + (uint32_t)(rl * GSTRIDE_B + kw + ((lane & 16) ? 16 : 0));
    const uint32_t aBase1 = aBase0 + (uint32_t)(16 * GSTRIDE_B);

    for (int it = 0; it <= T_STEPS; ++it) {
        const unsigned parity = (unsigned)(it & 1);

        // --- expect_tx for this step's two half-tiles ---
        if (tid == 0) {
            asm volatile("mbarrier.arrive.expect_tx.shared.b64 _, [%0], %1;"
                         :: "r"(mbar0), "r"(16 * ROW_BYTES) : "memory");
            asm volatile("mbarrier.arrive.expect_tx.shared.b64 _, [%0], %1;"
                         :: "r"(mbar1), "r"(16 * ROW_BYTES) : "memory");
        }

        // --- x prefetch (off critical path) ---
        float xr[EPT];
        if (it >= 1) {
            #pragma unroll
            for (int d = 0; d < EPT; ++d)
                if (ej[d] >= SDIM) {
                    size_t oi = ((size_t)(it - 1) * BATCH + (b0 + ebl[d])) * ODIM + (ej[d] - SDIM);
                    xr[d] = __ldcs(x + oi);
                }
        }

        // --- warp0 polls only the slot-set gating THIS rank's rows ---
        if (it > 0 && warp == 0) {
            const unsigned phase = (unsigned)it;
            for (;;) {
                unsigned v = ld_acq(&my_slots[lane]);
                if (__all_sync(0xffffffffu, v >= phase)) break;
            }
        }

        // --- tid0: issue 8 multicast row-copies (1KB each) ---
        if (tid == 0) {
            const uint8_t* Gc = g_G[it & 1];
            asm volatile("fence.proxy.async;" ::: "memory");
            #pragma unroll
            for (int rr = 0; rr < ROWS_PER_CTA; ++rr) {
                int r = rank * ROWS_PER_CTA + rr;
                const void* src = (const void*)(Gc + (size_t)(b0 + r) * SDIM);
                uint32_t dst = sGb + (uint32_t)(r * GSTRIDE_B);
                asm volatile(
                    "cp.async.bulk.shared::cluster.global.mbarrier::complete_tx::bytes"
                    ".multicast::cluster [%0], [%1], %2, [%3], %4;"
                    :: "r"(dst), "l"(src), "r"(ROW_BYTES), "r"(my_mbar),
                       "h"((unsigned short)((1u << CLUSTER) - 1u))
                    : "memory");
            }
        }

        float acc[2][5][4];
        #pragma unroll
        for (int mi = 0; mi < 2; ++mi)
            #pragma unroll
            for (int ni = 0; ni < 5; ++ni)
                #pragma unroll
                for (int q = 0; q < 4; ++q) acc[mi][ni][q] = 0.f;

        // --- half 0: rows 0-15 (4 k32 steps) ---
        mbar_wait(mbar0, parity);
        #pragma unroll
        for (int ks = 0; ks < 4; ++ks) {
            unsigned a[4];
            ldsm_x4(a, aBase0 + ks * 32);
            #pragma unroll
            for (int ni = 0; ni < 5; ++ni)
                mma_fp8(acc[0][ni], a, Breg[ks][ni][0], Breg[ks][ni][1]);
        }
        // --- half 1: rows 16-31 ---
        mbar_wait(mbar1, parity);
        #pragma unroll
        for (int ks = 0; ks < 4; ++ks) {
            unsigned a[4];
            ldsm_x4(a, aBase1 + ks * 32);
            #pragma unroll
            for (int ni = 0; ni < 5; ++ni)
                mma_fp8(acc[1][ni], a, Breg[ks][ni][0], Breg[ks][ni][1]);
        }

        // --- write per-warp partials (R4 layout) ---
        {
            float* p = sP + warp * (BT * JT);
            #pragma unroll
            for (int mi = 0; mi < 2; ++mi)
                #pragma unroll
                for (int ni = 0; ni < 5; ++ni) {
                    int r = mi * 16 + grp, cc = ni * 8 + tig * 2;
                    *(float2*)&p[r * JT + cc]       = make_float2(acc[mi][ni][0], acc[mi][ni][1]);
                    *(float2*)&p[(r + 8) * JT + cc] = make_float2(acc[mi][ni][2], acc[mi][ni][3]);
                }
        }
        __syncthreads();   // sync1: all partials in, all sG reads done

        // consumer-only CTAs: arrive early (off critical path)
        if (!producer && tid == 0) {
            st_rel(rel0, (unsigned)(it + 1));
            st_rel(rel1, (unsigned)(it + 1));
        }

        // --- split-K reduce (R4 form) + h update + tanh + fp8 G store ---
        uint8_t* Gn = g_G[(it + 1) & 1];
        float yv[EPT];
        #pragma unroll
        for (int d = 0; d < EPT; ++d) {
            int e = d * NTHREADS + tid;
            float y = sP[e];
            #pragma unroll
            for (int w = 1; w < NWARPS; ++w) y += sP[w * (BT * JT) + e];
            float ys = y * Y_INV;
            yv[d] = ys;
            if (ej[d] < SDIM) {
                float hv = 0.75f * hr[d] + 0.25f * (ys + bv[d]);
                hr[d] = hv;
                Gn[(size_t)(b0 + ebl[d]) * SDIM + ej[d]] = f32_to_e4m3(tanh_fast(hv) * 16.0f);
            }
        }

        if (producer) {
            __syncthreads();   // sync2: all G stores done
            if (tid == 0) {
                st_rel(rel0, (unsigned)(it + 1));
                st_rel(rel1, (unsigned)(it + 1));
            }
        }

        // --- outputs (off the critical path; x already in registers) ---
        if (it >= 1) {
            #pragma unroll
            for (int d = 0; d < EPT; ++d)
                if (ej[d] >= SDIM) {
                    size_t oi = ((size_t)(it - 1) * BATCH + (b0 + ebl[d])) * ODIM + (ej[d] - SDIM);
                    out[oi] = yv[d] + bv[d] - xr[d];
                }
        }
    }

    asm volatile("barrier.cluster.arrive.aligned;" ::: "memory");
    asm volatile("barrier.cluster.wait.aligned;"   ::: "memory");
}

// ---------------- launch ----------------
extern "C" void kernel_launch(void* const* d_in, const int* in_sizes, int n_in,
                              void* d_out, int out_size) {
    const float *x = nullptr, *h = nullptr, *wr = nullptr, *br = nullptr,
                *wo = nullptr, *bo = nullptr;
    for (int i = 0; i < n_in; ++i) {
        switch (in_sizes[i]) {
            case 512 * 128 * 256: x  = (const float*)d_in[i]; break;
            case 128 * 1024:      h  = (const float*)d_in[i]; break;
            case 1024 * 1024:     wr = (const float*)d_in[i]; break;
            case 1024:            br = (const float*)d_in[i]; break;
            case 256 * 1024:      wo = (const float*)d_in[i]; break;
            case 256:             bo = (const float*)d_in[i]; break;
            default: break;
        }
    }
    cudaFuncSetAttribute(trnn_persistent,
                         cudaFuncAttributeMaxDynamicSharedMemorySize, SMEM_TOTAL);
    trnn_init<<<512, 256>>>(wr, wo, h);
    trnn_persistent<<<NCTAS, NTHREADS, SMEM_TOTAL>>>(x, h, br, bo, (float*)d_out);
}

// round 14
// speedup vs baseline: 1.1554x; 1.1554x over previous
#include <cuda_runtime.h>
#include <cuda_bf16.h>
#include <cstdint>

// ---------------- problem dims (fixed by dataset) ----------------
#define T_STEPS 512
#define BATCH   128
#define SDIM    1024
#define ODIM    256
#define JDIM    (SDIM + ODIM)   // 1280

// ---------------- tiling ----------------
#define NB 4                 // batch tiles (independent recurrence groups)
#define NJ 32                // j tiles
#define BT 32                // batch rows per CTA
#define JT 40                // j cols per CTA
#define NCTAS (NB * NJ)      // 128 CTAs, one per SM
#define NTHREADS 256
#define NWARPS 8
#define KSLICE 128           // K slice per warp (split-K over 8 warps)
#define CLUSTER 4
#define ROWS_PER_CTA (BT / CLUSTER)   // 8 rows loaded+multicast per CTA
#define PAD 8
#define GSTRIDE (SDIM + PAD) // 1032 halves per smem row
#define ROW_BYTES (SDIM * 2) // 2048 B per G row in gmem
#define NPROD 26             // jtiles 0..25 produce h columns

// smem layout (bytes)
#define SG_BYTES (BT * GSTRIDE * 2)            // 66048
#define SP_BYTES (NWARPS * BT * JT * 4)        // 40960
#define SMEM_TOTAL (SG_BYTES + SP_BYTES + 16)  // + two mbarriers

// ---------------- device globals ----------------
__device__ __align__(16) __nv_bfloat16 g_W[(size_t)JDIM * SDIM];
__device__ __align__(16) __nv_bfloat16 g_G[2][(size_t)BATCH * SDIM];
__device__ unsigned g_slots0[NB * 32];  // arrival: G rows 0-15 stored / half0 reads done
__device__ unsigned g_slots1[NB * 32];  // arrival: G rows 16-31 stored / half1 reads done

// ---------------- helpers ----------------
__device__ __forceinline__ unsigned ld_acq(const unsigned* p) {
    unsigned v;
    asm volatile("ld.acquire.gpu.global.u32 %0, [%1];" : "=r"(v) : "l"(p));
    return v;
}
__device__ __forceinline__ void st_rel(unsigned* p, unsigned v) {
    asm volatile("st.release.gpu.global.u32 [%0], %1;" :: "l"(p), "r"(v) : "memory");
}
__device__ __forceinline__ float tanh_fast(float v) {
    float r;
    asm("tanh.approx.f32 %0, %1;" : "=f"(r) : "f"(v));
    return r;
}
__device__ __forceinline__ void mma16816(float c[4], const unsigned a[4],
                                         unsigned b0, unsigned b1) {
    asm volatile(
        "mma.sync.aligned.m16n8k16.row.col.f32.bf16.bf16.f32 "
        "{%0,%1,%2,%3}, {%4,%5,%6,%7}, {%8,%9}, {%0,%1,%2,%3};\n"
        : "+f"(c[0]), "+f"(c[1]), "+f"(c[2]), "+f"(c[3])
        : "r"(a[0]), "r"(a[1]), "r"(a[2]), "r"(a[3]), "r"(b0), "r"(b1));
}
__device__ __forceinline__ void ldsm_x4(unsigned a[4], uint32_t addr) {
    asm volatile("ldmatrix.sync.aligned.m8n8.x4.shared.b16 {%0,%1,%2,%3}, [%4];"
                 : "=r"(a[0]), "=r"(a[1]), "=r"(a[2]), "=r"(a[3]) : "r"(addr));
}
__device__ __forceinline__ void mbar_wait(uint32_t mbar, unsigned parity) {
    asm volatile(
        "{\n\t"
        ".reg .pred P;\n\t"
        "WL_%=:\n\t"
        "mbarrier.try_wait.parity.acquire.cta.shared::cta.b64 P, [%0], %1, 0x989680;\n\t"
        "@P bra.uni WD_%=;\n\t"
        "bra.uni WL_%=;\n\t"
        "WD_%=:\n\t"
        "}" :: "r"(mbar), "r"(parity) : "memory");
}

// ---------------- init: bf16 weights + G0 = tanh(h_init), reset barrier slots ----------------
__global__ void trnn_init(const float* __restrict__ w_r, const float* __restrict__ w_o,
                          const float* __restrict__ h_init) {
    size_t stride = (size_t)gridDim.x * blockDim.x;
    size_t i0 = (size_t)blockIdx.x * blockDim.x + threadIdx.x;
    const size_t WR_N = (size_t)SDIM * SDIM;
    const size_t W_N  = (size_t)JDIM * SDIM;
    for (size_t i = i0; i < W_N; i += stride) {
        float v = (i < WR_N) ? w_r[i] : w_o[i - WR_N];
        g_W[i] = __float2bfloat16(v);
    }
    for (size_t i = i0; i < (size_t)BATCH * SDIM; i += stride) {
        g_G[0][i] = __float2bfloat16(tanhf(h_init[i]));
    }
    if (i0 < NB * 32) { g_slots0[i0] = 0u; g_slots1[i0] = 0u; }
}

// ---------------- persistent kernel (R4 verbatim; TMA issue spread over warp0 lanes) ----------------
__global__ void __launch_bounds__(NTHREADS, 1) __cluster_dims__(CLUSTER, 1, 1)
trnn_persistent(const float* __restrict__ x, const float* __restrict__ h_init,
                const float* __restrict__ b_r, const float* __restrict__ b_o,
                float* __restrict__ out) {
    extern __shared__ char smem[];
    __nv_bfloat16* sG = (__nv_bfloat16*)smem;
    float* sP = (float*)(smem + SG_BYTES);
    uint32_t mbar0 = (uint32_t)__cvta_generic_to_shared(smem + SG_BYTES + SP_BYTES);
    uint32_t mbar1 = mbar0 + 8;

    const int tid  = threadIdx.x;
    const int warp = tid >> 5;
    const int lane = tid & 31;
    const int grp  = lane >> 2;
    const int tig  = lane & 3;
    const int btile = blockIdx.x >> 5;
    const int jtile = blockIdx.x & 31;
    const int rank  = blockIdx.x & (CLUSTER - 1);
    const int b0 = btile * BT;
    const int j0 = jtile * JT;
    const int kw = warp * KSLICE;
    const bool producer = (jtile < NPROD);

    unsigned* my_slots = (rank < 2) ? &g_slots0[btile * 32] : &g_slots1[btile * 32];
    unsigned* rel0 = &g_slots0[btile * 32 + jtile];
    unsigned* rel1 = &g_slots1[btile * 32 + jtile];
    const uint32_t my_mbar = (rank < 2) ? mbar0 : mbar1;

    if (tid == 0) {
        asm volatile("mbarrier.init.shared.b64 [%0], 1;" :: "r"(mbar0) : "memory");
        asm volatile("mbarrier.init.shared.b64 [%0], 1;" :: "r"(mbar1) : "memory");
    }
    __syncthreads();
    asm volatile("barrier.cluster.arrive.aligned;" ::: "memory");
    asm volatile("barrier.cluster.wait.aligned;"   ::: "memory");

    // --- per-thread persistent epilogue state (flat: e = d*256 + tid over 1280) ---
    int ej[5]; int ebl[5]; float hr[5]; float bv[5];
    #pragma unroll
    for (int d = 0; d < 5; ++d) {
        int e = d * NTHREADS + tid;
        int bl = e / JT, jl = e - bl * JT;
        int j = j0 + jl;
        ej[d] = j; ebl[d] = bl;
        if (j < SDIM) {
            hr[d] = h_init[(size_t)(b0 + bl) * SDIM + j];
            bv[d] = b_r[j];
        } else {
            hr[d] = 0.f;
            bv[d] = b_o[j - SDIM];
        }
    }

    // --- W fragments persistent in registers (80 regs/thread) ---
    unsigned Breg[8][5][2];
    #pragma unroll
    for (int ks = 0; ks < 8; ++ks) {
        #pragma unroll
        for (int ni = 0; ni < 5; ++ni) {
            int jr = ni * 8 + grp;
            const unsigned* wp = (const unsigned*)(g_W + (size_t)(j0 + jr) * SDIM + kw + ks * 16);
            Breg[ks][ni][0] = wp[tig];
            Breg[ks][ni][1] = wp[4 + tig];
        }
    }
    __syncthreads();

    // --- ldmatrix per-lane base addresses (rows 0-15 / 16-31) ---
    const uint32_t sGb = (uint32_t)__cvta_generic_to_shared(sG);
    const int rl = lane & 15;
    const int khalf = (lane & 16) ? 8 : 0;
    const uint32_t aBase0 = sGb + (uint32_t)((rl * GSTRIDE + kw + khalf) * 2);
    const uint32_t aBase1 = aBase0 + (uint32_t)(16 * GSTRIDE * 2);

    for (int it = 0; it <= T_STEPS; ++it) {
        const unsigned parity = (unsigned)(it & 1);

        // --- expect_tx for this step's two half-tiles ---
        if (tid == 0) {
            asm volatile("mbarrier.arrive.expect_tx.shared.b64 _, [%0], %1;"
                         :: "r"(mbar0), "r"(16 * ROW_BYTES) : "memory");
            asm volatile("mbarrier.arrive.expect_tx.shared.b64 _, [%0], %1;"
                         :: "r"(mbar1), "r"(16 * ROW_BYTES) : "memory");
        }

        // --- x prefetch (independent of G; off critical path) ---
        float xr[5];
        if (it >= 1) {
            #pragma unroll
            for (int d = 0; d < 5; ++d) {
                if (ej[d] >= SDIM) {
                    size_t oi = ((size_t)(it - 1) * BATCH + (b0 + ebl[d])) * ODIM + (ej[d] - SDIM);
                    xr[d] = __ldcs(x + oi);
                }
            }
        }

        // --- warp0: poll gating slots, then lanes 0-7 issue the 8 multicasts IN PARALLEL ---
        if (warp == 0) {
            if (it > 0) {
                const unsigned phase = (unsigned)it;
                for (;;) {
                    unsigned v = ld_acq(&my_slots[lane]);   // 32 coalesced slots
                    if (__all_sync(0xffffffffu, v >= phase)) break;
                }
            }
            if (lane < ROWS_PER_CTA) {
                const __nv_bfloat16* Gc = g_G[it & 1];
                asm volatile("fence.proxy.async;" ::: "memory");
                int r = rank * ROWS_PER_CTA + lane;
                const void* src = (const void*)(Gc + (size_t)(b0 + r) * SDIM);
                uint32_t dst = (uint32_t)__cvta_generic_to_shared(sG + r * GSTRIDE);
                asm volatile(
                    "cp.async.bulk.shared::cluster.global.mbarrier::complete_tx::bytes"
                    ".multicast::cluster [%0], [%1], %2, [%3], %4;"
                    :: "r"(dst), "l"(src), "r"(ROW_BYTES), "r"(my_mbar),
                       "h"((unsigned short)((1u << CLUSTER) - 1u))
                    : "memory");
            }
        }

        float acc[2][5][4];
        #pragma unroll
        for (int mi = 0; mi < 2; ++mi)
            #pragma unroll
            for (int ni = 0; ni < 5; ++ni)
                #pragma unroll
                for (int q = 0; q < 4; ++q) acc[mi][ni][q] = 0.f;

        // --- half 0: rows 0-15 ---
        mbar_wait(mbar0, parity);
        #pragma unroll
        for (int ks = 0; ks < 8; ++ks) {
            unsigned a[4];
            ldsm_x4(a, aBase0 + ks * 32);
            #pragma unroll
            for (int ni = 0; ni < 5; ++ni)
                mma16816(acc[0][ni], a, Breg[ks][ni][0], Breg[ks][ni][1]);
        }
        // --- half 1: rows 16-31 ---
        mbar_wait(mbar1, parity);
        #pragma unroll
        for (int ks = 0; ks < 8; ++ks) {
            unsigned a[4];
            ldsm_x4(a, aBase1 + ks * 32);
            #pragma unroll
            for (int ni = 0; ni < 5; ++ni)
                mma16816(acc[1][ni], a, Breg[ks][ni][0], Breg[ks][ni][1]);
        }

        // --- write per-warp partials ---
        {
            float* p = sP + warp * (BT * JT);
            #pragma unroll
            for (int mi = 0; mi < 2; ++mi)
                #pragma unroll
                for (int ni = 0; ni < 5; ++ni) {
                    int r = mi * 16 + grp, cc = ni * 8 + tig * 2;
                    *(float2*)&p[r * JT + cc]       = make_float2(acc[mi][ni][0], acc[mi][ni][1]);
                    *(float2*)&p[(r + 8) * JT + cc] = make_float2(acc[mi][ni][2], acc[mi][ni][3]);
                }
        }
        __syncthreads();   // sync1: all partials in, all sG reads done

        // consumer-only CTAs: arrive early (off critical path)
        if (!producer && tid == 0) {
            st_rel(rel0, (unsigned)(it + 1));
            st_rel(rel1, (unsigned)(it + 1));
        }

        // --- split-K reduce; h update + tanh + G store (critical path) ---
        __nv_bfloat16* Gn = g_G[(it + 1) & 1];
        float yv[5];
        #pragma unroll
        for (int d = 0; d < 5; ++d) {
            int e = d * NTHREADS + tid;
            float y = sP[e];
            #pragma unroll
            for (int w = 1; w < NWARPS; ++w) y += sP[w * (BT * JT) + e];
            yv[d] = y;
            if (ej[d] < SDIM) {
                float hv = 0.75f * hr[d] + 0.25f * (y + bv[d]);
                hr[d] = hv;
                Gn[(size_t)(b0 + ebl[d]) * SDIM + ej[d]] = __float2bfloat16(tanh_fast(hv));
            }
        }

        if (producer) {
            __syncthreads();   // sync2: all G stores done
            if (tid == 0) {
                st_rel(rel0, (unsigned)(it + 1));
                st_rel(rel1, (unsigned)(it + 1));
            }
        }

        // --- outputs (off the critical path; x already in registers) ---
        if (it >= 1) {
            #pragma unroll
            for (int d = 0; d < 5; ++d) {
                if (ej[d] >= SDIM) {
                    size_t oi = ((size_t)(it - 1) * BATCH + (b0 + ebl[d])) * ODIM + (ej[d] - SDIM);
                    out[oi] = yv[d] + bv[d] - xr[d];
                }
            }
        }
    }

    // no CTA may exit while peers' multicast writes into its smem are possible
    asm volatile("barrier.cluster.arrive.aligned;" ::: "memory");
    asm volatile("barrier.cluster.wait.aligned;"   ::: "memory");
}

// ---------------- launch ----------------
extern "C" void kernel_launch(void* const* d_in, const int* in_sizes, int n_in,
                              void* d_out, int out_size) {
    const float *x = nullptr, *h = nullptr, *wr = nullptr, *br = nullptr,
                *wo = nullptr, *bo = nullptr;
    for (int i = 0; i < n_in; ++i) {
        switch (in_sizes[i]) {
            case 512 * 128 * 256: x  = (const float*)d_in[i]; break;
            case 128 * 1024:      h  = (const float*)d_in[i]; break;
            case 1024 * 1024:     wr = (const float*)d_in[i]; break;
            case 1024:            br = (const float*)d_in[i]; break;
            case 256 * 1024:      wo = (const float*)d_in[i]; break;
            case 256:             bo = (const float*)d_in[i]; break;
            default: break;
        }
    }
    cudaFuncSetAttribute(trnn_persistent,
                         cudaFuncAttributeMaxDynamicSharedMemorySize, SMEM_TOTAL);
    trnn_init<<<512, 256>>>(wr, wo, h);
    trnn_persistent<<<NCTAS, NTHREADS, SMEM_TOTAL>>>(x, h, br, bo, (float*)d_out);
}

// round 15
// speedup vs baseline: 1.3098x; 1.1337x over previous
#include <cuda_runtime.h>
#include <cuda_bf16.h>
#include <cstdint>

// ---------------- problem dims (fixed by dataset) ----------------
#define T_STEPS 512
#define BATCH   128
#define SDIM    1024
#define ODIM    256
#define JDIM    (SDIM + ODIM)   // 1280

// ---------------- tiling ----------------
#define NB 4                 // batch tiles (independent recurrence groups)
#define NJ 32                // j tiles
#define BT 32                // batch rows per CTA
#define JT 40                // j cols per CTA
#define NCTAS (NB * NJ)      // 128 CTAs, one per SM
#define NTHREADS 256
#define NWARPS 8
#define CLUSTER 4
#define ROWS_PER_CTA (BT / CLUSTER)   // 8 rows loaded+multicast per CTA
#define PAD 8
#define GSTRIDE (SDIM + PAD) // 1032 halves per smem G row
#define ROW_BYTES (SDIM * 2) // 2048 B per G row in gmem
#define NPROD 26             // jtiles 0..25 produce h columns
// row-split: warps 0-3 rows 0-15 (K quarter = warp&3), warps 4-7 rows 16-31
#define KQ 256               // K elems per warp
#define SWCOLS 512           // smem-resident W: the upper 128 of each 256-K quarter
#define SWSTRIDE 520         // halves per sW row (512 + 8 pad)
#define SWW (SWSTRIDE / 2)   // 260 words
#define EHALF 640            // 16*40 elements per half

// smem layout (bytes)
#define SG_BYTES (BT * GSTRIDE * 2)            // 66048
#define SW_BYTES (JT * SWSTRIDE * 2)           // 41600
#define SP_BYTES (NWARPS * EHALF * 4)          // 20480
#define SMEM_TOTAL (SG_BYTES + SW_BYTES + SP_BYTES + 16)

// ---------------- device globals ----------------
__device__ __align__(16) __nv_bfloat16 g_W[(size_t)JDIM * SDIM];
__device__ __align__(16) __nv_bfloat16 g_G[2][(size_t)BATCH * SDIM];
__device__ unsigned g_slots0[NB * 32];  // G rows 0-15 stored / half0 sG free
__device__ unsigned g_slots1[NB * 32];  // G rows 16-31 stored / half1 sG free

// ---------------- helpers ----------------
__device__ __forceinline__ unsigned ld_acq(const unsigned* p) {
    unsigned v;
    asm volatile("ld.acquire.gpu.global.u32 %0, [%1];" : "=r"(v) : "l"(p));
    return v;
}
__device__ __forceinline__ void st_rel(unsigned* p, unsigned v) {
    asm volatile("st.release.gpu.global.u32 [%0], %1;" :: "l"(p), "r"(v) : "memory");
}
__device__ __forceinline__ float tanh_fast(float v) {
    float r;
    asm("tanh.approx.f32 %0, %1;" : "=f"(r) : "f"(v));
    return r;
}
__device__ __forceinline__ void mma16816(float c[4], const unsigned a[4],
                                         unsigned b0, unsigned b1) {
    asm volatile(
        "mma.sync.aligned.m16n8k16.row.col.f32.bf16.bf16.f32 "
        "{%0,%1,%2,%3}, {%4,%5,%6,%7}, {%8,%9}, {%0,%1,%2,%3};\n"
        : "+f"(c[0]), "+f"(c[1]), "+f"(c[2]), "+f"(c[3])
        : "r"(a[0]), "r"(a[1]), "r"(a[2]), "r"(a[3]), "r"(b0), "r"(b1));
}
__device__ __forceinline__ void ldsm_x4(unsigned a[4], uint32_t addr) {
    asm volatile("ldmatrix.sync.aligned.m8n8.x4.shared.b16 {%0,%1,%2,%3}, [%4];"
                 : "=r"(a[0]), "=r"(a[1]), "=r"(a[2]), "=r"(a[3]) : "r"(addr));
}
__device__ __forceinline__ void mbar_wait(uint32_t mbar, unsigned parity) {
    asm volatile(
        "{\n\t"
        ".reg .pred P;\n\t"
        "WL_%=:\n\t"
        "mbarrier.try_wait.parity.acquire.cta.shared::cta.b64 P, [%0], %1, 0x989680;\n\t"
        "@P bra.uni WD_%=;\n\t"
        "bra.uni WL_%=;\n\t"
        "WD_%=:\n\t"
        "}" :: "r"(mbar), "r"(parity) : "memory");
}
__device__ __forceinline__ void bar_named(int id) {
    asm volatile("bar.sync %0, 128;" :: "r"(id) : "memory");
}

// ---------------- init ----------------
__global__ void trnn_init(const float* __restrict__ w_r, const float* __restrict__ w_o,
                          const float* __restrict__ h_init) {
    size_t stride = (size_t)gridDim.x * blockDim.x;
    size_t i0 = (size_t)blockIdx.x * blockDim.x + threadIdx.x;
    const size_t WR_N = (size_t)SDIM * SDIM;
    const size_t W_N  = (size_t)JDIM * SDIM;
    for (size_t i = i0; i < W_N; i += stride) {
        float v = (i < WR_N) ? w_r[i] : w_o[i - WR_N];
        g_W[i] = __float2bfloat16(v);
    }
    for (size_t i = i0; i < (size_t)BATCH * SDIM; i += stride) {
        g_G[0][i] = __float2bfloat16(tanhf(h_init[i]));
    }
    if (i0 < NB * 32) { g_slots0[i0] = 0u; g_slots1[i0] = 0u; }
}

// ---------------- persistent kernel: row-owned halves, no in-loop __syncthreads ----------------
__global__ void __launch_bounds__(NTHREADS, 1) __cluster_dims__(CLUSTER, 1, 1)
trnn_persistent(const float* __restrict__ x, const float* __restrict__ h_init,
                const float* __restrict__ b_r, const float* __restrict__ b_o,
                float* __restrict__ out) {
    extern __shared__ char smem[];
    __nv_bfloat16* sG = (__nv_bfloat16*)smem;
    __nv_bfloat16* sW = (__nv_bfloat16*)(smem + SG_BYTES);
    float* sP = (float*)(smem + SG_BYTES + SW_BYTES);
    uint32_t mbar0 = (uint32_t)__cvta_generic_to_shared(smem + SG_BYTES + SW_BYTES + SP_BYTES);
    uint32_t mbar1 = mbar0 + 8;

    const int tid  = threadIdx.x;
    const int warp = tid >> 5;
    const int lane = tid & 31;
    const int grp  = lane >> 2;
    const int tig  = lane & 3;
    const int btile = blockIdx.x >> 5;
    const int jtile = blockIdx.x & 31;
    const int rank  = blockIdx.x & (CLUSTER - 1);
    const int b0 = btile * BT;
    const int j0 = jtile * JT;
    const int kq = warp & 3;             // K quarter [kq*256, kq*256+256)
    const int half = warp >> 2;          // 0: rows 0-15, 1: rows 16-31
    const int mybar = 1 + half;          // named barrier id
    const bool producer = (jtile < NPROD);

    unsigned* my_slots = (rank < 2) ? &g_slots0[btile * 32] : &g_slots1[btile * 32];
    unsigned* rel0 = &g_slots0[btile * 32 + jtile];
    unsigned* rel1 = &g_slots1[btile * 32 + jtile];
    const uint32_t my_mbar  = (rank < 2) ? mbar0 : mbar1;   // TMA target for my rows
    const uint32_t half_mbar = half ? mbar1 : mbar0;        // tile half this warp reads

    if (tid == 0) {
        asm volatile("mbarrier.init.shared.b64 [%0], 1;" :: "r"(mbar0) : "memory");
        asm volatile("mbarrier.init.shared.b64 [%0], 1;" :: "r"(mbar1) : "memory");
    }
    __syncthreads();
    asm volatile("barrier.cluster.arrive.aligned;" ::: "memory");
    asm volatile("barrier.cluster.wait.aligned;"   ::: "memory");

    // --- per-thread epilogue state: threads 0-127 own rows 0-15, 128-255 rows 16-31 ---
    // e_loc = d*128 + (tid&127) over 640 elems of this half
    const int tl = tid & 127;
    const int rowoff = (tid >> 7) * 16;
    int ej[5]; int erow[5]; float hr[5]; float bv[5];
    #pragma unroll
    for (int d = 0; d < 5; ++d) {
        int e = d * 128 + tl;
        int r = rowoff + e / JT;
        int j = j0 + (e % JT);
        ej[d] = j; erow[d] = r;
        if (j < SDIM) {
            hr[d] = h_init[(size_t)(b0 + r) * SDIM + j];
            bv[d] = b_r[j];
        } else {
            hr[d] = 0.f;
            bv[d] = b_o[j - SDIM];
        }
    }

    // --- W k-steps 0-7 of my quarter: registers (80 regs) ---
    unsigned Breg[8][5][2];
    #pragma unroll
    for (int ks = 0; ks < 8; ++ks) {
        #pragma unroll
        for (int ni = 0; ni < 5; ++ni) {
            int jr = j0 + ni * 8 + grp;
            const unsigned* wp = (const unsigned*)(g_W + (size_t)jr * SDIM + kq * KQ + ks * 16);
            Breg[ks][ni][0] = wp[tig];
            Breg[ks][ni][1] = wp[4 + tig];
        }
    }
    // --- W upper-half of every quarter: smem sW[40][512], col c -> k = (c>>7)*256+128+(c&127) ---
    for (int i = tid; i < JT * (SWCOLS / 8); i += NTHREADS) {
        int r = i >> 6, c8 = (i & 63) * 8;
        size_t gk = (size_t)(c8 >> 7) * 256 + 128 + (c8 & 127);
        uint4 v = *(const uint4*)(g_W + (size_t)(j0 + r) * SDIM + gk);
        *(uint4*)(sW + r * SWSTRIDE + c8) = v;
    }
    __syncthreads();

    const unsigned* sW32 = (const unsigned*)sW;
    const uint32_t sGb = (uint32_t)__cvta_generic_to_shared(sG);
    const int rl = lane & 15;
    const uint32_t aBase = sGb
        + (uint32_t)(((half * 16 + rl) * GSTRIDE + kq * KQ) * 2 + ((lane & 16) ? 16 : 0));

    for (int it = 0; it <= T_STEPS; ++it) {
        const unsigned parity = (unsigned)(it & 1);

        // --- expect_tx: warp0 -> mbar0, warp4 -> mbar1 (each in its dependent path) ---
        if (tid == 0)
            asm volatile("mbarrier.arrive.expect_tx.shared.b64 _, [%0], %1;"
                         :: "r"(mbar0), "r"(16 * ROW_BYTES) : "memory");
        if (tid == 128)
            asm volatile("mbarrier.arrive.expect_tx.shared.b64 _, [%0], %1;"
                         :: "r"(mbar1), "r"(16 * ROW_BYTES) : "memory");

        // --- x prefetch (off critical path) ---
        float xr[5];
        if (it >= 1) {
            #pragma unroll
            for (int d = 0; d < 5; ++d)
                if (ej[d] >= SDIM) {
                    size_t oi = ((size_t)(it - 1) * BATCH + (b0 + erow[d])) * ODIM + (ej[d] - SDIM);
                    xr[d] = __ldcs(x + oi);
                }
        }

        // --- warp0: poll my rank's gating slots, lanes 0-7 issue the 8 multicasts ---
        if (warp == 0) {
            if (it > 0) {
                const unsigned phase = (unsigned)it;
                for (;;) {
                    unsigned v = ld_acq(&my_slots[lane]);
                    if (__all_sync(0xffffffffu, v >= phase)) break;
                }
            }
            if (lane < ROWS_PER_CTA) {
                const __nv_bfloat16* Gc = g_G[it & 1];
                asm volatile("fence.proxy.async;" ::: "memory");
                int r = rank * ROWS_PER_CTA + lane;
                const void* src = (const void*)(Gc + (size_t)(b0 + r) * SDIM);
                uint32_t dst = (uint32_t)__cvta_generic_to_shared(sG + r * GSTRIDE);
                asm volatile(
                    "cp.async.bulk.shared::cluster.global.mbarrier::complete_tx::bytes"
                    ".multicast::cluster [%0], [%1], %2, [%3], %4;"
                    :: "r"(dst), "l"(src), "r"(ROW_BYTES), "r"(my_mbar),
                       "h"((unsigned short)((1u << CLUSTER) - 1u))
                    : "memory");
            }
        }

        // --- wait only this warp's row-half; mma over full K quarter (16 k-steps) ---
        mbar_wait(half_mbar, parity);

        float acc[5][4];
        #pragma unroll
        for (int ni = 0; ni < 5; ++ni)
            #pragma unroll
            for (int q = 0; q < 4; ++q) acc[ni][q] = 0.f;

        #pragma unroll
        for (int ks = 0; ks < 8; ++ks) {        // k-steps 0-7: W in registers
            unsigned a[4];
            ldsm_x4(a, aBase + ks * 32);
            #pragma unroll
            for (int ni = 0; ni < 5; ++ni)
                mma16816(acc[ni], a, Breg[ks][ni][0], Breg[ks][ni][1]);
        }
        #pragma unroll
        for (int ks = 0; ks < 8; ++ks) {        // k-steps 8-15: W from smem
            unsigned a[4];
            ldsm_x4(a, aBase + 128 * 2 + ks * 32);
            const int kb = kq * 64 + ks * 8;
            #pragma unroll
            for (int ni = 0; ni < 5; ++ni) {
                int jr = ni * 8 + grp;
                unsigned b0w = sW32[jr * SWW + kb + tig];
                unsigned b1w = sW32[jr * SWW + kb + 4 + tig];
                mma16816(acc[ni], a, b0w, b1w);
            }
        }

        // --- partials: slot `warp` holds this warp's 16x40 tile ---
        {
            float* p = sP + warp * EHALF;
            #pragma unroll
            for (int ni = 0; ni < 5; ++ni) {
                int cc = ni * 8 + tig * 2;
                *(float2*)&p[grp * JT + cc]       = make_float2(acc[ni][0], acc[ni][1]);
                *(float2*)&p[(grp + 8) * JT + cc] = make_float2(acc[ni][2], acc[ni][3]);
            }
        }
        bar_named(mybar);   // half-barrier A: my half's partials in, my half's sG reads done

        // non-producers: this half's sG is free -> release now (data part vacuous)
        if (!producer) {
            if (tid == 0)   st_rel(rel0, (unsigned)(it + 1));
            if (tid == 128) st_rel(rel1, (unsigned)(it + 1));
        }

        // --- 4-partial reduce + h update + tanh + G store (within my half) ---
        __nv_bfloat16* Gn = g_G[(it + 1) & 1];
        const float* pb = sP + (half * 4) * EHALF;
        float yv[5];
        #pragma unroll
        for (int d = 0; d < 5; ++d) {
            int e = d * 128 + tl;
            float y = (pb[e] + pb[EHALF + e]) + (pb[2 * EHALF + e] + pb[3 * EHALF + e]);
            yv[d] = y;
            if (ej[d] < SDIM) {
                float hv = 0.75f * hr[d] + 0.25f * (y + bv[d]);
                hr[d] = hv;
                Gn[(size_t)(b0 + erow[d]) * SDIM + ej[d]] = __float2bfloat16(tanh_fast(hv));
            }
        }

        if (producer) {
            bar_named(mybar);   // half-barrier B: my half's G stores done
            if (tid == 0)   st_rel(rel0, (unsigned)(it + 1));
            if (tid == 128) st_rel(rel1, (unsigned)(it + 1));
        }

        // --- outputs (off the critical path) ---
        if (it >= 1) {
            #pragma unroll
            for (int d = 0; d < 5; ++d)
                if (ej[d] >= SDIM) {
                    size_t oi = ((size_t)(it - 1) * BATCH + (b0 + erow[d])) * ODIM + (ej[d] - SDIM);
                    out[oi] = yv[d] + bv[d] - xr[d];
                }
        }
    }

    __syncthreads();
    asm volatile("barrier.cluster.arrive.aligned;" ::: "memory");
    asm volatile("barrier.cluster.wait.aligned;"   ::: "memory");
}

// ---------------- launch ----------------
extern "C" void kernel_launch(void* const* d_in, const int* in_sizes, int n_in,
                              void* d_out, int out_size) {
    const float *x = nullptr, *h = nullptr, *wr = nullptr, *br = nullptr,
                *wo = nullptr, *bo = nullptr;
    for (int i = 0; i < n_in; ++i) {
        switch (in_sizes[i]) {
            case 512 * 128 * 256: x  = (const float*)d_in[i]; break;
            case 128 * 1024:      h  = (const float*)d_in[i]; break;
            case 1024 * 1024:     wr = (const float*)d_in[i]; break;
            case 1024:            br = (const float*)d_in[i]; break;
            case 256 * 1024:      wo = (const float*)d_in[i]; break;
            case 256:             bo = (const float*)d_in[i]; break;
            default: break;
        }
    }
    cudaFuncSetAttribute(trnn_persistent,
                         cudaFuncAttributeMaxDynamicSharedMemorySize, SMEM_TOTAL);
    trnn_init<<<512, 256>>>(wr, wo, h);
    trnn_persistent<<<NCTAS, NTHREADS, SMEM_TOTAL>>>(x, h, br, bo, (float*)d_out);
}

// round 16
// speedup vs baseline: 1.3367x; 1.0206x over previous
#include <cuda_runtime.h>
#include <cuda_bf16.h>
#include <cstdint>

// ---------------- problem dims (fixed by dataset) ----------------
#define T_STEPS 512
#define BATCH   128
#define SDIM    1024
#define ODIM    256
#define JDIM    (SDIM + ODIM)   // 1280

// ---------------- tiling ----------------
#define NB 4                 // batch tiles (independent recurrence groups)
#define NJ 32                // j tiles
#define BT 32                // batch rows per CTA
#define JT 40                // j cols per CTA
#define NCTAS (NB * NJ)      // 128 CTAs, one per SM
#define NTHREADS 256
#define NWARPS 8
#define CLUSTER 4
#define ROWS_PER_CTA (BT / CLUSTER)   // 8 rows loaded+multicast per CTA
#define PAD 8
#define GSTRIDE (SDIM + PAD) // 1032 halves per smem G row
#define ROW_BYTES (SDIM * 2) // 2048 B per G row in gmem
#define NPROD 26             // jtiles 0..25 produce h columns
// row-split: warps 0-3 rows 0-15 (K quarter = warp&3), warps 4-7 rows 16-31
#define KQ 256               // K elems per warp
#define EHALF 640            // 16*40 elements per half
// pre-swizzled smem W (upper k-half of each quarter): 4*8*5*32 uint2 pairs
#define SW_PAIRS 5120

// smem layout (bytes)
#define SG_BYTES (BT * GSTRIDE * 2)            // 66048
#define SW_BYTES (SW_PAIRS * 8)                // 40960
#define SP_BYTES (NWARPS * EHALF * 4)          // 20480
#define SMEM_TOTAL (SG_BYTES + SW_BYTES + SP_BYTES + 16)

// ---------------- device globals ----------------
__device__ __align__(16) __nv_bfloat16 g_W[(size_t)JDIM * SDIM];
__device__ __align__(16) __nv_bfloat16 g_G[2][(size_t)BATCH * SDIM];
__device__ unsigned g_slots0[NB * 32];  // G rows 0-15 stored / half0 sG free
__device__ unsigned g_slots1[NB * 32];  // G rows 16-31 stored / half1 sG free

// ---------------- helpers ----------------
__device__ __forceinline__ unsigned ld_acq(const unsigned* p) {
    unsigned v;
    asm volatile("ld.acquire.gpu.global.u32 %0, [%1];" : "=r"(v) : "l"(p));
    return v;
}
__device__ __forceinline__ void st_rel(unsigned* p, unsigned v) {
    asm volatile("st.release.gpu.global.u32 [%0], %1;" :: "l"(p), "r"(v) : "memory");
}
__device__ __forceinline__ float tanh_fast(float v) {
    float r;
    asm("tanh.approx.f32 %0, %1;" : "=f"(r) : "f"(v));
    return r;
}
__device__ __forceinline__ void mma16816(float c[4], const unsigned a[4],
                                         unsigned b0, unsigned b1) {
    asm volatile(
        "mma.sync.aligned.m16n8k16.row.col.f32.bf16.bf16.f32 "
        "{%0,%1,%2,%3}, {%4,%5,%6,%7}, {%8,%9}, {%0,%1,%2,%3};\n"
        : "+f"(c[0]), "+f"(c[1]), "+f"(c[2]), "+f"(c[3])
        : "r"(a[0]), "r"(a[1]), "r"(a[2]), "r"(a[3]), "r"(b0), "r"(b1));
}
__device__ __forceinline__ void ldsm_x4(unsigned a[4], uint32_t addr) {
    asm volatile("ldmatrix.sync.aligned.m8n8.x4.shared.b16 {%0,%1,%2,%3}, [%4];"
                 : "=r"(a[0]), "=r"(a[1]), "=r"(a[2]), "=r"(a[3]) : "r"(addr));
}
__device__ __forceinline__ void mbar_wait(uint32_t mbar, unsigned parity) {
    asm volatile(
        "{\n\t"
        ".reg .pred P;\n\t"
        "WL_%=:\n\t"
        "mbarrier.try_wait.parity.acquire.cta.shared::cta.b64 P, [%0], %1, 0x989680;\n\t"
        "@P bra.uni WD_%=;\n\t"
        "bra.uni WL_%=;\n\t"
        "WD_%=:\n\t"
        "}" :: "r"(mbar), "r"(parity) : "memory");
}
__device__ __forceinline__ void bar_named(int id) {
    asm volatile("bar.sync %0, 128;" :: "r"(id) : "memory");
}

// ---------------- init ----------------
__global__ void trnn_init(const float* __restrict__ w_r, const float* __restrict__ w_o,
                          const float* __restrict__ h_init) {
    size_t stride = (size_t)gridDim.x * blockDim.x;
    size_t i0 = (size_t)blockIdx.x * blockDim.x + threadIdx.x;
    const size_t WR_N = (size_t)SDIM * SDIM;
    const size_t W_N  = (size_t)JDIM * SDIM;
    for (size_t i = i0; i < W_N; i += stride) {
        float v = (i < WR_N) ? w_r[i] : w_o[i - WR_N];
        g_W[i] = __float2bfloat16(v);
    }
    for (size_t i = i0; i < (size_t)BATCH * SDIM; i += stride) {
        g_G[0][i] = __float2bfloat16(tanhf(h_init[i]));
    }
    if (i0 < NB * 32) { g_slots0[i0] = 0u; g_slots1[i0] = 0u; }
}

// ---------------- persistent kernel: row-owned halves + aligned poll + LDS.64 W ----------------
__global__ void __launch_bounds__(NTHREADS, 1) __cluster_dims__(CLUSTER, 1, 1)
trnn_persistent(const float* __restrict__ x, const float* __restrict__ h_init,
                const float* __restrict__ b_r, const float* __restrict__ b_o,
                float* __restrict__ out) {
    extern __shared__ char smem[];
    __nv_bfloat16* sG = (__nv_bfloat16*)smem;
    uint2* sW64 = (uint2*)(smem + SG_BYTES);
    float* sP = (float*)(smem + SG_BYTES + SW_BYTES);
    uint32_t mbar0 = (uint32_t)__cvta_generic_to_shared(smem + SG_BYTES + SW_BYTES + SP_BYTES);
    uint32_t mbar1 = mbar0 + 8;

    const int tid  = threadIdx.x;
    const int warp = tid >> 5;
    const int lane = tid & 31;
    const int grp  = lane >> 2;
    const int tig  = lane & 3;
    const int btile = blockIdx.x >> 5;
    const int jtile = blockIdx.x & 31;
    const int rank  = blockIdx.x & (CLUSTER - 1);
    const int b0 = btile * BT;
    const int j0 = jtile * JT;
    const int kq = warp & 3;             // K quarter [kq*256, kq*256+256)
    const int half = warp >> 2;          // 0: rows 0-15, 1: rows 16-31
    const int mybar = 1 + half;          // named barrier id
    const bool producer = (jtile < NPROD);
    // poll/TMA warp aligned with the half its rank's rows feed
    const int pollwarp = (rank < 2) ? 0 : 4;

    unsigned* my_slots = (rank < 2) ? &g_slots0[btile * 32] : &g_slots1[btile * 32];
    unsigned* rel0 = &g_slots0[btile * 32 + jtile];
    unsigned* rel1 = &g_slots1[btile * 32 + jtile];
    const uint32_t my_mbar  = (rank < 2) ? mbar0 : mbar1;   // TMA target for my rows
    const uint32_t half_mbar = half ? mbar1 : mbar0;        // tile half this warp reads

    if (tid == 0) {
        asm volatile("mbarrier.init.shared.b64 [%0], 1;" :: "r"(mbar0) : "memory");
        asm volatile("mbarrier.init.shared.b64 [%0], 1;" :: "r"(mbar1) : "memory");
    }
    __syncthreads();
    asm volatile("barrier.cluster.arrive.aligned;" ::: "memory");
    asm volatile("barrier.cluster.wait.aligned;"   ::: "memory");

    // --- per-thread epilogue state: threads 0-127 own rows 0-15, 128-255 rows 16-31 ---
    const int tl = tid & 127;
    const int rowoff = (tid >> 7) * 16;
    int ej[5]; int erow[5]; float hr[5]; float bv[5];
    #pragma unroll
    for (int d = 0; d < 5; ++d) {
        int e = d * 128 + tl;
        int r = rowoff + e / JT;
        int j = j0 + (e % JT);
        ej[d] = j; erow[d] = r;
        if (j < SDIM) {
            hr[d] = h_init[(size_t)(b0 + r) * SDIM + j];
            bv[d] = b_r[j];
        } else {
            hr[d] = 0.f;
            bv[d] = b_o[j - SDIM];
        }
    }

    // --- W k-steps 0-7 of my quarter: registers (80 regs) ---
    unsigned Breg[8][5][2];
    #pragma unroll
    for (int ks = 0; ks < 8; ++ks) {
        #pragma unroll
        for (int ni = 0; ni < 5; ++ni) {
            int jr = j0 + ni * 8 + grp;
            const unsigned* wp = (const unsigned*)(g_W + (size_t)jr * SDIM + kq * KQ + ks * 16);
            Breg[ks][ni][0] = wp[tig];
            Breg[ks][ni][1] = wp[4 + tig];
        }
    }
    // --- W upper k-half of every quarter: pre-swizzled pairs, slot = lane (bank-clean) ---
    // pair i: kq=i/1280, ks=(i/160)%8, ni=(i/32)%5, slot=i%32 -> (grp_s,tig_s)
    for (int i = tid; i < SW_PAIRS; i += NTHREADS) {
        int kq_ = i / 1280;
        int rem = i - kq_ * 1280;
        int ks_ = rem / 160;
        int rem2 = rem - ks_ * 160;
        int ni_ = rem2 >> 5;
        int sl = rem2 & 31;
        int grp_s = sl >> 2, tig_s = sl & 3;
        int jr = j0 + ni_ * 8 + grp_s;
        const unsigned* wp = (const unsigned*)(g_W + (size_t)jr * SDIM + kq_ * KQ + 128 + ks_ * 16);
        sW64[i] = make_uint2(wp[tig_s], wp[4 + tig_s]);
    }
    __syncthreads();

    const uint32_t sGb = (uint32_t)__cvta_generic_to_shared(sG);
    const int rl = lane & 15;
    const uint32_t aBase = sGb
        + (uint32_t)(((half * 16 + rl) * GSTRIDE + kq * KQ) * 2 + ((lane & 16) ? 16 : 0));
    const uint2* myW = sW64 + (size_t)kq * 1280 + lane;   // + ks*160 + ni*32 at use

    for (int it = 0; it <= T_STEPS; ++it) {
        const unsigned parity = (unsigned)(it & 1);

        // --- expect_tx: warp0 -> mbar0, warp4 -> mbar1 ---
        if (tid == 0)
            asm volatile("mbarrier.arrive.expect_tx.shared.b64 _, [%0], %1;"
                         :: "r"(mbar0), "r"(16 * ROW_BYTES) : "memory");
        if (tid == 128)
            asm volatile("mbarrier.arrive.expect_tx.shared.b64 _, [%0], %1;"
                         :: "r"(mbar1), "r"(16 * ROW_BYTES) : "memory");

        // --- x prefetch (off critical path) ---
        float xr[5];
        if (it >= 1) {
            #pragma unroll
            for (int d = 0; d < 5; ++d)
                if (ej[d] >= SDIM) {
                    size_t oi = ((size_t)(it - 1) * BATCH + (b0 + erow[d])) * ODIM + (ej[d] - SDIM);
                    xr[d] = __ldcs(x + oi);
                }
        }

        // --- aligned poll warp: poll my rank's gating slots, lanes 0-7 issue multicasts ---
        if (warp == pollwarp) {
            if (it > 0) {
                const unsigned phase = (unsigned)it;
                for (;;) {
                    unsigned v = ld_acq(&my_slots[lane]);
                    if (__all_sync(0xffffffffu, v >= phase)) break;
                }
            }
            if (lane < ROWS_PER_CTA) {
                const __nv_bfloat16* Gc = g_G[it & 1];
                asm volatile("fence.proxy.async;" ::: "memory");
                int r = rank * ROWS_PER_CTA + lane;
                const void* src = (const void*)(Gc + (size_t)(b0 + r) * SDIM);
                uint32_t dst = (uint32_t)__cvta_generic_to_shared(sG + r * GSTRIDE);
                asm volatile(
                    "cp.async.bulk.shared::cluster.global.mbarrier::complete_tx::bytes"
                    ".multicast::cluster [%0], [%1], %2, [%3], %4;"
                    :: "r"(dst), "l"(src), "r"(ROW_BYTES), "r"(my_mbar),
                       "h"((unsigned short)((1u << CLUSTER) - 1u))
                    : "memory");
            }
        }

        // --- wait only this warp's row-half; mma over full K quarter (16 k-steps) ---
        mbar_wait(half_mbar, parity);

        float acc[5][4];
        #pragma unroll
        for (int ni = 0; ni < 5; ++ni)
            #pragma unroll
            for (int q = 0; q < 4; ++q) acc[ni][q] = 0.f;

        #pragma unroll
        for (int ks = 0; ks < 8; ++ks) {        // k-steps 0-7: W in registers
            unsigned a[4];
            ldsm_x4(a, aBase + ks * 32);
            #pragma unroll
            for (int ni = 0; ni < 5; ++ni)
                mma16816(acc[ni], a, Breg[ks][ni][0], Breg[ks][ni][1]);
        }
        #pragma unroll
        for (int ks = 0; ks < 8; ++ks) {        // k-steps 8-15: W via conflict-free LDS.64
            unsigned a[4];
            ldsm_x4(a, aBase + 256 + ks * 32);
            #pragma unroll
            for (int ni = 0; ni < 5; ++ni) {
                uint2 w = myW[ks * 160 + ni * 32];
                mma16816(acc[ni], a, w.x, w.y);
            }
        }

        // --- partials: slot `warp` holds this warp's 16x40 tile ---
        {
            float* p = sP + warp * EHALF;
            #pragma unroll
            for (int ni = 0; ni < 5; ++ni) {
                int cc = ni * 8 + tig * 2;
                *(float2*)&p[grp * JT + cc]       = make_float2(acc[ni][0], acc[ni][1]);
                *(float2*)&p[(grp + 8) * JT + cc] = make_float2(acc[ni][2], acc[ni][3]);
            }
        }
        bar_named(mybar);   // half-barrier A: my half's partials in, my half's sG reads done

        // non-producers: this half's sG is free -> release now (data part vacuous)
        if (!producer) {
            if (tid == 0)   st_rel(rel0, (unsigned)(it + 1));
            if (tid == 128) st_rel(rel1, (unsigned)(it + 1));
        }

        // --- 4-partial reduce + h update + tanh + G store (within my half) ---
        __nv_bfloat16* Gn = g_G[(it + 1) & 1];
        const float* pb = sP + (half * 4) * EHALF;
        float yv[5];
        #pragma unroll
        for (int d = 0; d < 5; ++d) {
            int e = d * 128 + tl;
            float y = (pb[e] + pb[EHALF + e]) + (pb[2 * EHALF + e] + pb[3 * EHALF + e]);
            yv[d] = y;
            if (ej[d] < SDIM) {
                float hv = 0.75f * hr[d] + 0.25f * (y + bv[d]);
                hr[d] = hv;
                Gn[(size_t)(b0 + erow[d]) * SDIM + ej[d]] = __float2bfloat16(tanh_fast(hv));
            }
        }

        if (producer) {
            bar_named(mybar);   // half-barrier B: my half's G stores done
            if (tid == 0)   st_rel(rel0, (unsigned)(it + 1));
            if (tid == 128) st_rel(rel1, (unsigned)(it + 1));
        }

        // --- outputs (off the critical path) ---
        if (it >= 1) {
            #pragma unroll
            for (int d = 0; d < 5; ++d)
                if (ej[d] >= SDIM) {
                    size_t oi = ((size_t)(it - 1) * BATCH + (b0 + erow[d])) * ODIM + (ej[d] - SDIM);
                    out[oi] = yv[d] + bv[d] - xr[d];
                }
        }
    }

    __syncthreads();
    asm volatile("barrier.cluster.arrive.aligned;" ::: "memory");
    asm volatile("barrier.cluster.wait.aligned;"   ::: "memory");
}

// ---------------- launch ----------------
extern "C" void kernel_launch(void* const* d_in, const int* in_sizes, int n_in,
                              void* d_out, int out_size) {
    const float *x = nullptr, *h = nullptr, *wr = nullptr, *br = nullptr,
                *wo = nullptr, *bo = nullptr;
    for (int i = 0; i < n_in; ++i) {
        switch (in_sizes[i]) {
            case 512 * 128 * 256: x  = (const float*)d_in[i]; break;
            case 128 * 1024:      h  = (const float*)d_in[i]; break;
            case 1024 * 1024:     wr = (const float*)d_in[i]; break;
            case 1024:            br = (const float*)d_in[i]; break;
            case 256 * 1024:      wo = (const float*)d_in[i]; break;
            case 256:             bo = (const float*)d_in[i]; break;
            default: break;
        }
    }
    cudaFuncSetAttribute(trnn_persistent,
                         cudaFuncAttributeMaxDynamicSharedMemorySize, SMEM_TOTAL);
    trnn_init<<<512, 256>>>(wr, wo, h);
    trnn_persistent<<<NCTAS, NTHREADS, SMEM_TOTAL>>>(x, h, br, bo, (float*)d_out);
}